// round 5
// baseline (speedup 1.0000x reference)
#include <cuda_runtime.h>
#include <math.h>

#define NN 10000
#define NE 160000
#define ET (NN + NE)

// ---------------- scratch (device globals; referenced by symbol ONLY in device code) ----------------
__device__ float g_feat[NN * 256];     // layer input features (row-major, stride = fin)
__device__ float g_hbuf[NN * 2048];    // h = X @ W   (row-major, stride = H*C)
__device__ float g_hs[NN * 16];        // per-node per-head source attention dot
__device__ float g_hd[NN * 16];        // per-node per-head dest attention dot
__device__ int   g_cnt[NN];
__device__ int   g_cur[NN];
__device__ int   g_off[NN + 1];
__device__ int   g_csr[ET];
__device__ float g_cb1[64 * 64 * 64];
__device__ float g_cb2[64 * 64 * 64];
__device__ float g_gf[24];
__device__ unsigned char g_bflags[NN];
__device__ int   g_is64;

__device__ __forceinline__ float selu_f(float v) {
    const float sc = 1.0507009873554805f;
    const float al = 1.6732632423543772f;
    return v > 0.f ? sc * v : sc * al * (expf(v) - 1.f);
}

// Edge index may arrive as int64 (reference dtype) or harness-narrowed int32.
__device__ __forceinline__ int edge_at(const void* ei, int idx) {
    if (g_is64) return (int)((const long long*)ei)[idx];
    return ((const int*)ei)[idx];
}

// ---------------- dtype detection (single block) ----------------
__global__ void detect_k(const void* __restrict__ ei) {
    __shared__ int nz;
    if (threadIdx.x == 0) nz = 0;
    __syncthreads();
    const int* p = (const int*)ei;
    int found = 0;
    for (int j = threadIdx.x; j < 4096; j += 256)
        if (p[2 * j + 1] != 0) found = 1;   // hi halves all zero <=> int64
    if (found) atomicOr(&nz, 1);
    __syncthreads();
    if (threadIdx.x == 0) g_is64 = nz ? 0 : 1;
}

// ---------------- CSR build (by dst, with self loops) ----------------
__global__ void csr_init_k() {
    int i = blockIdx.x * 256 + threadIdx.x;
    if (i < NN) { g_cnt[i] = 1; g_cur[i] = 0; }   // count 1 = self loop
}

__global__ void csr_count_k(const void* __restrict__ ei) {
    int e = blockIdx.x * 256 + threadIdx.x;
    if (e < NE) {
        int d = edge_at(ei, NE + e);
        atomicAdd(&g_cnt[d], 1);
    }
}

__global__ void csr_scan_k() {
    __shared__ int part[256];
    int tid = threadIdx.x;
    const int per = 40;                // 256*40 = 10240 >= 10000
    int start = tid * per;
    int s = 0;
    for (int j = 0; j < per; j++) { int idx = start + j; if (idx < NN) s += g_cnt[idx]; }
    part[tid] = s;
    __syncthreads();
    if (tid == 0) {
        int run = 0;
        for (int k = 0; k < 256; k++) { int t = part[k]; part[k] = run; run += t; }
    }
    __syncthreads();
    int run = part[tid];
    for (int j = 0; j < per; j++) {
        int idx = start + j;
        if (idx < NN) { g_off[idx] = run; run += g_cnt[idx]; }
    }
    if (start <= NN - 1 && NN - 1 < start + per) g_off[NN] = run;
}

__global__ void csr_fill_k(const void* __restrict__ ei) {
    int idx = blockIdx.x * 256 + threadIdx.x;
    if (idx >= ET) return;
    int s, d;
    if (idx < NN) { s = idx; d = idx; }                 // self loop
    else {
        int e = idx - NN;
        s = edge_at(ei, e);
        d = edge_at(ei, NE + e);
    }
    int pos = g_off[d] + atomicAdd(&g_cur[d], 1);
    g_csr[pos] = s;
}

// ---------------- CNN ----------------
// in_sel: 0 = external (cf), 1 = g_cb1, 2 = g_cb2; out_sel: 1 = g_cb1, 2 = g_cb2
__global__ void conv3x3_k(const float* __restrict__ ext_in, int in_sel, int out_sel,
                          const float* __restrict__ w, const float* __restrict__ b, int IC) {
    __shared__ float ws[64 * 9];
    const float* in = (in_sel == 0) ? ext_in : (in_sel == 1 ? g_cb1 : g_cb2);
    float* out = (out_sel == 1) ? g_cb1 : g_cb2;
    int oc = blockIdx.y;
    for (int idx = threadIdx.x; idx < IC * 9; idx += 256) ws[idx] = w[oc * IC * 9 + idx];
    __syncthreads();
    int p = blockIdx.x * 256 + threadIdx.x;   // 16 blocks * 256 = 4096 pixels
    int y = p >> 6, xx = p & 63;
    float acc = b[oc];
    for (int ic = 0; ic < IC; ic++) {
        const float* ip = in + ic * 4096;
        const float* wp = ws + ic * 9;
#pragma unroll
        for (int ky = 0; ky < 3; ky++) {
            int iy = y + ky - 1;
            if ((unsigned)iy >= 64u) continue;
#pragma unroll
            for (int kx = 0; kx < 3; kx++) {
                int ix = xx + kx - 1;
                if ((unsigned)ix >= 64u) continue;
                acc += ip[iy * 64 + ix] * wp[ky * 3 + kx];
            }
        }
    }
    out[oc * 4096 + p] = selu_f(acc);
}

__global__ void avgpool_k() {   // reads g_cb2, writes g_gf
    __shared__ float red[256];
    int c = blockIdx.x;
    float s = 0.f;
    for (int p = threadIdx.x; p < 4096; p += 256) s += g_cb2[c * 4096 + p];
    red[threadIdx.x] = s;
    __syncthreads();
    for (int o = 128; o > 0; o >>= 1) {
        if (threadIdx.x < o) red[threadIdx.x] += red[threadIdx.x + o];
        __syncthreads();
    }
    if (threadIdx.x == 0) g_gf[c] = red[0] * (1.f / 4096.f);
}

// ---------------- layer-1 input + boundary flags ----------------
__global__ void build_in_k(const float* __restrict__ x) {
    int i = blockIdx.x * 256 + threadIdx.x;
    if (i >= NN) return;
    float x0 = x[i * 10], x1 = x[i * 10 + 1];
    unsigned char f = 0;
    if (x0 == 1.f) f |= 1;   // up
    if (x0 == 0.f) f |= 2;   // down
    if (x1 == 0.f) f |= 4;   // left
    if (x1 == 1.f) f |= 8;   // right
    g_bflags[i] = f;
#pragma unroll
    for (int c = 0; c < 24; c++) g_feat[i * 34 + c] = g_gf[c];
#pragma unroll
    for (int c = 0; c < 10; c++) g_feat[i * 34 + 24 + c] = x[i * 10 + c];
}

// ---------------- SGEMM: g_hbuf[N,M] = g_feat[N,K] @ B[K,M], fp32, 64x64x16 tiles ----------------
__global__ void sgemm_k(const float* __restrict__ B, int N, int K, int M) {
    __shared__ float As[16][64];
    __shared__ float Bs[16][64];
    int tid = threadIdx.x;
    int tx = tid & 15, ty = tid >> 4;
    int row0 = blockIdx.y * 64, col0 = blockIdx.x * 64;
    float acc[4][4];
#pragma unroll
    for (int i = 0; i < 4; i++)
#pragma unroll
        for (int j = 0; j < 4; j++) acc[i][j] = 0.f;

    for (int k0 = 0; k0 < K; k0 += 16) {
#pragma unroll
        for (int j = 0; j < 4; j++) {
            int idx = tid + j * 256;
            int r = idx >> 4, kk = idx & 15;
            int gr = row0 + r, gk = k0 + kk;
            As[kk][r] = (gr < N && gk < K) ? g_feat[(size_t)gr * K + gk] : 0.f;
        }
#pragma unroll
        for (int j = 0; j < 4; j++) {
            int idx = tid + j * 256;
            int kk = idx >> 6, c = idx & 63;
            int gk = k0 + kk, gc = col0 + c;
            Bs[kk][c] = (gk < K && gc < M) ? B[(size_t)gk * M + gc] : 0.f;
        }
        __syncthreads();
#pragma unroll
        for (int kk = 0; kk < 16; kk++) {
            float a[4], b[4];
#pragma unroll
            for (int i = 0; i < 4; i++) a[i] = As[kk][ty * 4 + i];
#pragma unroll
            for (int j = 0; j < 4; j++) b[j] = Bs[kk][tx * 4 + j];
#pragma unroll
            for (int i = 0; i < 4; i++)
#pragma unroll
                for (int j = 0; j < 4; j++) acc[i][j] += a[i] * b[j];
        }
        __syncthreads();
    }
#pragma unroll
    for (int i = 0; i < 4; i++) {
        int gr = row0 + ty * 4 + i;
        if (gr >= N) continue;
#pragma unroll
        for (int j = 0; j < 4; j++) {
            int gc = col0 + tx * 4 + j;
            if (gc < M) g_hbuf[(size_t)gr * M + gc] = acc[i][j];
        }
    }
}

// ---------------- per-node attention dots hs/hd (reads g_hbuf) ----------------
__global__ void attn_dots_k(const float* __restrict__ as_, const float* __restrict__ ad_,
                            int H, int C) {
    int i = blockIdx.x;
    int warp = threadIdx.x >> 5, lane = threadIdx.x & 31;
    const float* hrow = g_hbuf + (size_t)i * H * C;
    for (int hh = warp; hh < H; hh += 8) {
        float ps = 0.f, pd = 0.f;
        for (int c = lane; c < C; c += 32) {
            float v = hrow[hh * C + c];
            ps += v * as_[hh * C + c];
            pd += v * ad_[hh * C + c];
        }
#pragma unroll
        for (int o = 16; o; o >>= 1) {
            ps += __shfl_xor_sync(0xffffffffu, ps, o);
            pd += __shfl_xor_sync(0xffffffffu, pd, o);
        }
        if (lane == 0) { g_hs[i * H + hh] = ps; g_hd[i * H + hh] = pd; }
    }
}

// ---------------- GAT aggregation: softmax over incoming edges + weighted sum ----------------
// One block per dst node. Reads g_hbuf/g_hs/g_hd/g_csr. Writes g_feat, or outp when FINAL.
template <int H, int C, bool FINAL>
__global__ void gat_agg_k(const float* __restrict__ bias, const float* __restrict__ x,
                          float* __restrict__ outp) {
    constexpr int HC = H * C;
    constexpr int NT = 256;
    constexpr int R = (HC + NT - 1) / NT;
    constexpr int CH = 32;
    __shared__ float s_m[H], s_z[H], s_hdi[H];
    __shared__ int   s_src[CH];
    __shared__ float s_e[CH * H];
    __shared__ float s_agg[HC];

    int i = blockIdx.x;
    int tid = threadIdx.x;
    int e0 = g_off[i];
    int deg = g_off[i + 1] - e0;
    if (tid < H) s_hdi[tid] = g_hd[i * H + tid];
    __syncthreads();

    // Pass A: online softmax stats per head
    float m_run = -1e30f, z_run = 0.f;
    for (int c0 = 0; c0 < deg; c0 += CH) {
        int cl = min(CH, deg - c0);
        if (tid < cl) s_src[tid] = g_csr[e0 + c0 + tid];
        __syncthreads();
        for (int idx = tid; idx < cl * H; idx += NT) {
            int ce = idx / H, hh = idx - ce * H;
            float v = g_hs[s_src[ce] * H + hh] + s_hdi[hh];
            s_e[idx] = v > 0.f ? v : 0.2f * v;
        }
        __syncthreads();
        if (tid < H) {
            for (int ce = 0; ce < cl; ce++) {
                float v = s_e[ce * H + tid];
                float mn = fmaxf(m_run, v);
                z_run = z_run * expf(m_run - mn) + expf(v - mn);
                m_run = mn;
            }
        }
        __syncthreads();
    }
    if (tid < H) { s_m[tid] = m_run; s_z[tid] = z_run; }
    __syncthreads();

    // Pass B: alpha-weighted gather of h[src]
    float acc[R];
#pragma unroll
    for (int r = 0; r < R; r++) acc[r] = 0.f;

    for (int c0 = 0; c0 < deg; c0 += CH) {
        int cl = min(CH, deg - c0);
        if (tid < cl) s_src[tid] = g_csr[e0 + c0 + tid];
        __syncthreads();
        for (int idx = tid; idx < cl * H; idx += NT) {
            int ce = idx / H, hh = idx - ce * H;
            float v = g_hs[s_src[ce] * H + hh] + s_hdi[hh];
            v = v > 0.f ? v : 0.2f * v;
            s_e[idx] = expf(v - s_m[hh]) / (s_z[hh] + 1e-16f);
        }
        __syncthreads();
        for (int ce = 0; ce < cl; ce++) {
            const float* hrow = g_hbuf + (size_t)s_src[ce] * HC;
#pragma unroll
            for (int r = 0; r < R; r++) {
                int j = tid + r * NT;
                if (HC >= NT * (r + 1) || j < HC)
                    acc[r] += s_e[ce * H + (j / C)] * hrow[j];
            }
        }
        __syncthreads();
    }

#pragma unroll
    for (int r = 0; r < R; r++) {
        int j = tid + r * NT;
        if (HC >= NT * (r + 1) || j < HC) s_agg[j] = acc[r];
    }
    __syncthreads();

    unsigned char f = g_bflags[i];
    for (int c = tid; c < C; c += NT) {
        float v = 0.f;
#pragma unroll
        for (int hh = 0; hh < H; hh++) v += s_agg[hh * C + c];
        v = v * (1.f / H) + bias[c];
        v = selu_f(v);
        if (FINAL) v += x[i * 10 + c];
        if (c == 0)      v = (f & 2) ? 0.f : ((f & 1) ? 1.f : v);
        else if (c == 1) v = (f & 8) ? 1.f : ((f & 4) ? 0.f : v);
        if (FINAL) outp[(size_t)i * C + c] = v;
        else       g_feat[(size_t)i * C + c] = v;
    }
}

// ---------------- host launch ----------------
extern "C" void kernel_launch(void* const* d_in, const int* in_sizes, int n_in,
                              void* d_out, int out_size) {
    const float* x  = (const float*)d_in[0];
    const void*  ei = d_in[1];
    const float* cf = (const float*)d_in[2];
    const float* cw[4]  = {(const float*)d_in[3], (const float*)d_in[5],
                           (const float*)d_in[7], (const float*)d_in[9]};
    const float* cbi[4] = {(const float*)d_in[4], (const float*)d_in[6],
                           (const float*)d_in[8], (const float*)d_in[10]};
    const float *gw[5], *gas[5], *gad[5], *gb[5];
    for (int l = 0; l < 5; l++) {
        gw[l]  = (const float*)d_in[11 + 4 * l];
        gas[l] = (const float*)d_in[12 + 4 * l];
        gad[l] = (const float*)d_in[13 + 4 * l];
        gb[l]  = (const float*)d_in[14 + 4 * l];
    }
    float* out = (float*)d_out;

    // Edge-index dtype detection, then CSR by dst (with self loops)
    detect_k<<<1, 256>>>(ei);
    csr_init_k<<<(NN + 255) / 256, 256>>>();
    csr_count_k<<<(NE + 255) / 256, 256>>>(ei);
    csr_scan_k<<<1, 256>>>();
    csr_fill_k<<<(ET + 255) / 256, 256>>>(ei);

    // CNN (ping-pong g_cb1/g_cb2 via selectors)
    conv3x3_k<<<dim3(16, 16), 256>>>(cf, 0, 1, cw[0], cbi[0], 4);
    conv3x3_k<<<dim3(16, 32), 256>>>(nullptr, 1, 2, cw[1], cbi[1], 16);
    conv3x3_k<<<dim3(16, 64), 256>>>(nullptr, 2, 1, cw[2], cbi[2], 32);
    conv3x3_k<<<dim3(16, 24), 256>>>(nullptr, 1, 2, cw[3], cbi[3], 64);
    avgpool_k<<<24, 256>>>();
    build_in_k<<<(NN + 255) / 256, 256>>>(x);

    const int fins[5] = {34, 64, 128, 256, 128};
    const int Hs[5]   = {8, 16, 8, 8, 16};
    const int Cs[5]   = {64, 128, 256, 128, 2};

    for (int l = 0; l < 5; l++) {
        int HC = Hs[l] * Cs[l];
        dim3 gg((HC + 63) / 64, (NN + 63) / 64);
        sgemm_k<<<gg, 256>>>(gw[l], NN, fins[l], HC);
        attn_dots_k<<<NN, 256>>>(gas[l], gad[l], Hs[l], Cs[l]);
        switch (l) {
            case 0: gat_agg_k<8, 64, false><<<NN, 256>>>(gb[0], x, nullptr); break;
            case 1: gat_agg_k<16, 128, false><<<NN, 256>>>(gb[1], x, nullptr); break;
            case 2: gat_agg_k<8, 256, false><<<NN, 256>>>(gb[2], x, nullptr); break;
            case 3: gat_agg_k<8, 128, false><<<NN, 256>>>(gb[3], x, nullptr); break;
            case 4: gat_agg_k<16, 2, true><<<NN, 256>>>(gb[4], x, out); break;
        }
    }
}

// round 7
// speedup vs baseline: 1.1741x; 1.1741x over previous
#include <cuda_runtime.h>
#include <math.h>

#define NN 10000
#define NE 160000
#define ET (NN + NE)

// ---------------- scratch (device globals; referenced by symbol ONLY in device code) ----------------
__device__ float g_feat[NN * 256];     // layer input features (row-major, stride = fin)
__device__ float g_hbuf[NN * 2048];    // h = X @ W   (row-major, stride = H*C)
__device__ float g_hs[NN * 16];        // per-node per-head source attention dot
__device__ float g_hd[NN * 16];        // per-node per-head dest attention dot
__device__ int   g_cnt[NN];
__device__ int   g_cur[NN];
__device__ int   g_off[NN + 1];
__device__ int   g_csr[ET];
__device__ float g_cb1[64 * 64 * 64];
__device__ float g_cb2[64 * 64 * 64];
__device__ float g_gf[24];
__device__ unsigned char g_bflags[NN];
__device__ int   g_is64;

__device__ __forceinline__ float selu_f(float v) {
    const float sc = 1.0507009873554805f;
    const float al = 1.6732632423543772f;
    return v > 0.f ? sc * v : sc * al * (expf(v) - 1.f);
}

// Edge index may arrive as int64 (reference dtype) or harness-narrowed int32.
__device__ __forceinline__ int edge_at(const void* ei, int idx) {
    if (g_is64) return (int)((const long long*)ei)[idx];
    return ((const int*)ei)[idx];
}

// ---------------- CSR init + dtype detection (fused) ----------------
__global__ void init_detect_k(const void* __restrict__ ei) {
    int i = blockIdx.x * 256 + threadIdx.x;
    if (i < NN) { g_cnt[i] = 1; g_cur[i] = 0; }   // count 1 = self loop
    if (blockIdx.x == 0) {
        __shared__ int nz;
        if (threadIdx.x == 0) nz = 0;
        __syncthreads();
        const int* p = (const int*)ei;
        int found = 0;
        for (int j = threadIdx.x; j < 4096; j += 256)
            if (p[2 * j + 1] != 0) found = 1;   // hi halves all zero <=> int64
        if (found) atomicOr(&nz, 1);
        __syncthreads();
        if (threadIdx.x == 0) g_is64 = nz ? 0 : 1;
    }
}

// ---------------- CSR build (by dst, with self loops) ----------------
__global__ void csr_count_k(const void* __restrict__ ei) {
    int e = blockIdx.x * 256 + threadIdx.x;
    if (e < NE) {
        int d = edge_at(ei, NE + e);
        atomicAdd(&g_cnt[d], 1);
    }
}

__global__ void csr_scan_k() {   // 1024 threads, warp-shuffle scan
    __shared__ int wsum[32];
    int tid = threadIdx.x;
    const int per = 10;          // 1024*10 = 10240 >= 10000
    int start = tid * per;
    int s = 0;
#pragma unroll
    for (int j = 0; j < per; j++) { int idx = start + j; if (idx < NN) s += g_cnt[idx]; }
    int lane = tid & 31, warp = tid >> 5;
    int v = s;
#pragma unroll
    for (int o = 1; o < 32; o <<= 1) {
        int t = __shfl_up_sync(0xffffffffu, v, o);
        if (lane >= o) v += t;
    }
    if (lane == 31) wsum[warp] = v;
    __syncthreads();
    if (warp == 0) {
        int w = wsum[lane];
#pragma unroll
        for (int o = 1; o < 32; o <<= 1) {
            int t = __shfl_up_sync(0xffffffffu, w, o);
            if (lane >= o) w += t;
        }
        wsum[lane] = w;
    }
    __syncthreads();
    int base = (warp ? wsum[warp - 1] : 0) + (v - s);   // exclusive prefix for this thread
    int run = base;
#pragma unroll
    for (int j = 0; j < per; j++) {
        int idx = start + j;
        if (idx < NN) { g_off[idx] = run; run += g_cnt[idx]; }
    }
    if (tid == 0) g_off[NN] = wsum[31];
}

__global__ void csr_fill_k(const void* __restrict__ ei) {
    int idx = blockIdx.x * 256 + threadIdx.x;
    if (idx >= ET) return;
    int s, d;
    if (idx < NN) { s = idx; d = idx; }                 // self loop
    else {
        int e = idx - NN;
        s = edge_at(ei, e);
        d = edge_at(ei, NE + e);
    }
    int pos = g_off[d] + atomicAdd(&g_cur[d], 1);
    g_csr[pos] = s;
}

// ---------------- CNN ----------------
__global__ void conv3x3_k(const float* __restrict__ ext_in, int in_sel, int out_sel,
                          const float* __restrict__ w, const float* __restrict__ b, int IC) {
    __shared__ float ws[64 * 9];
    const float* in = (in_sel == 0) ? ext_in : (in_sel == 1 ? g_cb1 : g_cb2);
    float* out = (out_sel == 1) ? g_cb1 : g_cb2;
    int oc = blockIdx.y;
    for (int idx = threadIdx.x; idx < IC * 9; idx += 256) ws[idx] = w[oc * IC * 9 + idx];
    __syncthreads();
    int p = blockIdx.x * 256 + threadIdx.x;   // 16 blocks * 256 = 4096 pixels
    int y = p >> 6, xx = p & 63;
    float acc = b[oc];
    for (int ic = 0; ic < IC; ic++) {
        const float* ip = in + ic * 4096;
        const float* wp = ws + ic * 9;
#pragma unroll
        for (int ky = 0; ky < 3; ky++) {
            int iy = y + ky - 1;
            if ((unsigned)iy >= 64u) continue;
#pragma unroll
            for (int kx = 0; kx < 3; kx++) {
                int ix = xx + kx - 1;
                if ((unsigned)ix >= 64u) continue;
                acc += ip[iy * 64 + ix] * wp[ky * 3 + kx];
            }
        }
    }
    out[oc * 4096 + p] = selu_f(acc);
}

__global__ void avgpool_k() {   // reads g_cb2, writes g_gf
    __shared__ float red[256];
    int c = blockIdx.x;
    float s = 0.f;
    for (int p = threadIdx.x; p < 4096; p += 256) s += g_cb2[c * 4096 + p];
    red[threadIdx.x] = s;
    __syncthreads();
    for (int o = 128; o > 0; o >>= 1) {
        if (threadIdx.x < o) red[threadIdx.x] += red[threadIdx.x + o];
        __syncthreads();
    }
    if (threadIdx.x == 0) g_gf[c] = red[0] * (1.f / 4096.f);
}

// ---------------- layer-1 input + boundary flags ----------------
__global__ void build_in_k(const float* __restrict__ x) {
    int i = blockIdx.x * 256 + threadIdx.x;
    if (i >= NN) return;
    float x0 = x[i * 10], x1 = x[i * 10 + 1];
    unsigned char f = 0;
    if (x0 == 1.f) f |= 1;   // up
    if (x0 == 0.f) f |= 2;   // down
    if (x1 == 0.f) f |= 4;   // left
    if (x1 == 1.f) f |= 8;   // right
    g_bflags[i] = f;
#pragma unroll
    for (int c = 0; c < 24; c++) g_feat[i * 34 + c] = g_gf[c];
#pragma unroll
    for (int c = 0; c < 10; c++) g_feat[i * 34 + 24 + c] = x[i * 10 + c];
}

// ---------------- SGEMM v2: g_hbuf[N,M] = g_feat[N,K] @ B[K,M] ----------------
// 128x64 tile, 256 threads, 8x4 accum/thread, double-buffered smem, float4 I/O.
__global__ void __launch_bounds__(256) sgemm_k(const float* __restrict__ B, int N, int K, int M) {
    __shared__ float As[2][16][128];
    __shared__ float Bs[2][16][64];
    int tid = threadIdx.x;
    int tx = tid & 15, ty = tid >> 4;
    int row0 = blockIdx.y * 128, col0 = blockIdx.x * 64;

    // A loader mapping: 128 rows x 16 kk; thread -> (row ar, kk group aq*8..aq*8+7)
    int ar = tid & 127;
    int aq = tid >> 7;
    // B loader mapping: 16 kk x 64 cols; thread -> (kk bk, 4 cols at bc)
    int bk = tid >> 4;
    int bc = (tid & 15) * 4;

    const bool kfull = (K % 16 == 0);
    const int ntiles = (K + 15) / 16;

    float acc[8][4];
#pragma unroll
    for (int i = 0; i < 8; i++)
#pragma unroll
        for (int j = 0; j < 4; j++) acc[i][j] = 0.f;

    float ra[8], rb[4];
    int agr = row0 + ar;
    int bgc = col0 + bc;

    auto load_tile = [&](int kt) {
        int k0 = kt * 16;
        if (kfull) {
            if (agr < N) {
                const float* p = &g_feat[(size_t)agr * K + k0 + aq * 8];
                float4 v0 = *(const float4*)p;
                float4 v1 = *(const float4*)(p + 4);
                ra[0] = v0.x; ra[1] = v0.y; ra[2] = v0.z; ra[3] = v0.w;
                ra[4] = v1.x; ra[5] = v1.y; ra[6] = v1.z; ra[7] = v1.w;
            } else {
#pragma unroll
                for (int j = 0; j < 8; j++) ra[j] = 0.f;
            }
        } else {
#pragma unroll
            for (int j = 0; j < 8; j++) {
                int gk = k0 + aq * 8 + j;
                ra[j] = (agr < N && gk < K) ? g_feat[(size_t)agr * K + gk] : 0.f;
            }
        }
        int gk = k0 + bk;
        if (gk < K && bgc < M) {
            float4 v = *(const float4*)&B[(size_t)gk * M + bgc];
            rb[0] = v.x; rb[1] = v.y; rb[2] = v.z; rb[3] = v.w;
        } else {
#pragma unroll
            for (int j = 0; j < 4; j++) rb[j] = 0.f;
        }
    };
    auto store_tile = [&](int nb) {
#pragma unroll
        for (int j = 0; j < 8; j++) As[nb][aq * 8 + j][ar] = ra[j];
        *(float4*)&Bs[nb][bk][bc] = make_float4(rb[0], rb[1], rb[2], rb[3]);
    };

    load_tile(0);
    store_tile(0);
    __syncthreads();

    for (int kt = 0; kt < ntiles; kt++) {
        int buf = kt & 1;
        bool more = (kt + 1 < ntiles);
        if (more) load_tile(kt + 1);
#pragma unroll
        for (int kk = 0; kk < 16; kk++) {
            float a[8], b[4];
#pragma unroll
            for (int i = 0; i < 8; i++) a[i] = As[buf][kk][ty * 8 + i];
#pragma unroll
            for (int j = 0; j < 4; j++) b[j] = Bs[buf][kk][tx * 4 + j];
#pragma unroll
            for (int i = 0; i < 8; i++)
#pragma unroll
                for (int j = 0; j < 4; j++) acc[i][j] += a[i] * b[j];
        }
        if (more) store_tile(buf ^ 1);
        __syncthreads();
    }

    int gc = col0 + tx * 4;
    if (gc < M) {
#pragma unroll
        for (int i = 0; i < 8; i++) {
            int gr = row0 + ty * 8 + i;
            if (gr < N)
                *(float4*)&g_hbuf[(size_t)gr * M + gc] =
                    make_float4(acc[i][0], acc[i][1], acc[i][2], acc[i][3]);
        }
    }
}

// ---------------- per-node attention dots hs/hd (reads g_hbuf) ----------------
__global__ void attn_dots_k(const float* __restrict__ as_, const float* __restrict__ ad_,
                            int H, int C) {
    int i = blockIdx.x;
    int warp = threadIdx.x >> 5, lane = threadIdx.x & 31;
    const float* hrow = g_hbuf + (size_t)i * H * C;
    for (int hh = warp; hh < H; hh += 8) {
        float ps = 0.f, pd = 0.f;
        for (int c = lane; c < C; c += 32) {
            float v = hrow[hh * C + c];
            ps += v * as_[hh * C + c];
            pd += v * ad_[hh * C + c];
        }
#pragma unroll
        for (int o = 16; o; o >>= 1) {
            ps += __shfl_xor_sync(0xffffffffu, ps, o);
            pd += __shfl_xor_sync(0xffffffffu, pd, o);
        }
        if (lane == 0) { g_hs[i * H + hh] = ps; g_hd[i * H + hh] = pd; }
    }
}

// ---------------- GAT aggregation: softmax over incoming edges + weighted sum ----------------
template <int H, int C, bool FINAL>
__global__ void gat_agg_k(const float* __restrict__ bias, const float* __restrict__ x,
                          float* __restrict__ outp) {
    constexpr int HC = H * C;
    constexpr int NT = 256;
    constexpr int R = (HC + NT - 1) / NT;
    constexpr int CH = 32;
    __shared__ float s_m[H], s_z[H], s_hdi[H];
    __shared__ int   s_src[CH];
    __shared__ float s_e[CH * H];
    __shared__ float s_agg[HC];

    int i = blockIdx.x;
    int tid = threadIdx.x;
    int e0 = g_off[i];
    int deg = g_off[i + 1] - e0;
    if (tid < H) s_hdi[tid] = g_hd[i * H + tid];
    __syncthreads();

    // Pass A: online softmax stats per head
    float m_run = -1e30f, z_run = 0.f;
    for (int c0 = 0; c0 < deg; c0 += CH) {
        int cl = min(CH, deg - c0);
        if (tid < cl) s_src[tid] = g_csr[e0 + c0 + tid];
        __syncthreads();
        for (int idx = tid; idx < cl * H; idx += NT) {
            int ce = idx / H, hh = idx - ce * H;
            float v = g_hs[s_src[ce] * H + hh] + s_hdi[hh];
            s_e[idx] = v > 0.f ? v : 0.2f * v;
        }
        __syncthreads();
        if (tid < H) {
            for (int ce = 0; ce < cl; ce++) {
                float v = s_e[ce * H + tid];
                float mn = fmaxf(m_run, v);
                z_run = z_run * expf(m_run - mn) + expf(v - mn);
                m_run = mn;
            }
        }
        __syncthreads();
    }
    if (tid < H) { s_m[tid] = m_run; s_z[tid] = z_run; }
    __syncthreads();

    // Pass B: alpha-weighted gather of h[src]
    float acc[R];
#pragma unroll
    for (int r = 0; r < R; r++) acc[r] = 0.f;

    for (int c0 = 0; c0 < deg; c0 += CH) {
        int cl = min(CH, deg - c0);
        if (tid < cl) s_src[tid] = g_csr[e0 + c0 + tid];
        __syncthreads();
        for (int idx = tid; idx < cl * H; idx += NT) {
            int ce = idx / H, hh = idx - ce * H;
            float v = g_hs[s_src[ce] * H + hh] + s_hdi[hh];
            v = v > 0.f ? v : 0.2f * v;
            s_e[idx] = expf(v - s_m[hh]) / (s_z[hh] + 1e-16f);
        }
        __syncthreads();
        for (int ce = 0; ce < cl; ce++) {
            const float* hrow = g_hbuf + (size_t)s_src[ce] * HC;
#pragma unroll
            for (int r = 0; r < R; r++) {
                int j = tid + r * NT;
                if (HC >= NT * (r + 1) || j < HC)
                    acc[r] += s_e[ce * H + (j / C)] * hrow[j];
            }
        }
        __syncthreads();
    }

#pragma unroll
    for (int r = 0; r < R; r++) {
        int j = tid + r * NT;
        if (HC >= NT * (r + 1) || j < HC) s_agg[j] = acc[r];
    }
    __syncthreads();

    unsigned char f = g_bflags[i];
    for (int c = tid; c < C; c += NT) {
        float v = 0.f;
#pragma unroll
        for (int hh = 0; hh < H; hh++) v += s_agg[hh * C + c];
        v = v * (1.f / H) + bias[c];
        v = selu_f(v);
        if (FINAL) v += x[i * 10 + c];
        if (c == 0)      v = (f & 2) ? 0.f : ((f & 1) ? 1.f : v);
        else if (c == 1) v = (f & 8) ? 1.f : ((f & 4) ? 0.f : v);
        if (FINAL) outp[(size_t)i * C + c] = v;
        else       g_feat[(size_t)i * C + c] = v;
    }
}

// ---------------- host launch ----------------
extern "C" void kernel_launch(void* const* d_in, const int* in_sizes, int n_in,
                              void* d_out, int out_size) {
    const float* x  = (const float*)d_in[0];
    const void*  ei = d_in[1];
    const float* cf = (const float*)d_in[2];
    const float* cw[4]  = {(const float*)d_in[3], (const float*)d_in[5],
                           (const float*)d_in[7], (const float*)d_in[9]};
    const float* cbi[4] = {(const float*)d_in[4], (const float*)d_in[6],
                           (const float*)d_in[8], (const float*)d_in[10]};
    const float *gw[5], *gas[5], *gad[5], *gb[5];
    for (int l = 0; l < 5; l++) {
        gw[l]  = (const float*)d_in[11 + 4 * l];
        gas[l] = (const float*)d_in[12 + 4 * l];
        gad[l] = (const float*)d_in[13 + 4 * l];
        gb[l]  = (const float*)d_in[14 + 4 * l];
    }
    float* out = (float*)d_out;

    // CSR by dst (with self loops); dtype detection fused into init
    init_detect_k<<<(NN + 255) / 256, 256>>>(ei);
    csr_count_k<<<(NE + 255) / 256, 256>>>(ei);
    csr_scan_k<<<1, 1024>>>();
    csr_fill_k<<<(ET + 255) / 256, 256>>>(ei);

    // CNN (ping-pong g_cb1/g_cb2 via selectors)
    conv3x3_k<<<dim3(16, 16), 256>>>(cf, 0, 1, cw[0], cbi[0], 4);
    conv3x3_k<<<dim3(16, 32), 256>>>(nullptr, 1, 2, cw[1], cbi[1], 16);
    conv3x3_k<<<dim3(16, 64), 256>>>(nullptr, 2, 1, cw[2], cbi[2], 32);
    conv3x3_k<<<dim3(16, 24), 256>>>(nullptr, 1, 2, cw[3], cbi[3], 64);
    avgpool_k<<<24, 256>>>();
    build_in_k<<<(NN + 255) / 256, 256>>>(x);

    const int fins[5] = {34, 64, 128, 256, 128};
    const int Hs[5]   = {8, 16, 8, 8, 16};
    const int Cs[5]   = {64, 128, 256, 128, 2};

    for (int l = 0; l < 5; l++) {
        int HC = Hs[l] * Cs[l];
        dim3 gg((HC + 63) / 64, (NN + 127) / 128);
        sgemm_k<<<gg, 256>>>(gw[l], NN, fins[l], HC);
        attn_dots_k<<<NN, 256>>>(gas[l], gad[l], Hs[l], Cs[l]);
        switch (l) {
            case 0: gat_agg_k<8, 64, false><<<NN, 256>>>(gb[0], x, nullptr); break;
            case 1: gat_agg_k<16, 128, false><<<NN, 256>>>(gb[1], x, nullptr); break;
            case 2: gat_agg_k<8, 256, false><<<NN, 256>>>(gb[2], x, nullptr); break;
            case 3: gat_agg_k<8, 128, false><<<NN, 256>>>(gb[3], x, nullptr); break;
            case 4: gat_agg_k<16, 2, true><<<NN, 256>>>(gb[4], x, out); break;
        }
    }
}